// round 17
// baseline (speedup 1.0000x reference)
#include <cuda_runtime.h>
#include <cuda_fp16.h>
#include <cstdint>

static constexpr int T_TOK = 8192;
static constexpr int H_DIM = 2048;
static constexpr int E_NUM = 8;
static constexpr int I_DIM = 1024;
static constexpr int NPAIR = T_TOK * 2;

// ---------------- scratch (static device globals; no allocations) ----------------
__device__ __align__(128) __half g_xh[(size_t)T_TOK * H_DIM];   // x in fp16 (router writes)
__device__ __align__(128) __half g_yh[(size_t)NPAIR * I_DIM];   // silu(g)*u, fp16
__device__ int   g_topidx[NPAIR];
__device__ float g_topw[NPAIR];
__device__ float g_wbuf[NPAIR];                                 // bucket row -> combine weight
__device__ int   g_bucket[NPAIR];                               // bucket row -> token id
__device__ int   g_counts[E_NUM];
__device__ int   g_offsets[E_NUM + 1];
__device__ int   g_cursors[E_NUM];
__device__ int   g_done[E_NUM * 64];                            // per (expert, m-block) GEMM1 completions

// ---------------- PTX helpers ----------------
#define SWZ128(o) ((o) ^ (((o) >> 3) & 0x70))

__device__ __forceinline__ uint32_t h2u(__half2 h) {
    return *reinterpret_cast<uint32_t*>(&h);
}
__device__ __forceinline__ void cp16(uint32_t dst, const void* src) {
    asm volatile("cp.async.cg.shared.global [%0], [%1], 16;" :: "r"(dst), "l"(src) : "memory");
}
__device__ __forceinline__ void cp_commit() {
    asm volatile("cp.async.commit_group;" ::: "memory");
}
template <int N>
__device__ __forceinline__ void cp_wait() {
    asm volatile("cp.async.wait_group %0;" :: "n"(N) : "memory");
}
__device__ __forceinline__ void ldsm4(uint32_t* d, uint32_t addr) {
    asm volatile("ldmatrix.sync.aligned.m8n8.x4.shared.b16 {%0,%1,%2,%3}, [%4];"
                 : "=r"(d[0]), "=r"(d[1]), "=r"(d[2]), "=r"(d[3]) : "r"(addr));
}
__device__ __forceinline__ void mma16816(float* c, const uint32_t* a, uint32_t b0, uint32_t b1) {
    asm volatile(
        "mma.sync.aligned.m16n8k16.row.col.f32.f16.f16.f32 "
        "{%0,%1,%2,%3}, {%4,%5,%6,%7}, {%8,%9}, {%0,%1,%2,%3};"
        : "+f"(c[0]), "+f"(c[1]), "+f"(c[2]), "+f"(c[3])
        : "r"(a[0]), "r"(a[1]), "r"(a[2]), "r"(a[3]), "r"(b0), "r"(b1));
}

// ---------------- tiny setup kernels ----------------
__global__ void init_kernel() {
    int i = threadIdx.x;
    if (i < E_NUM) { g_counts[i] = 0; g_cursors[i] = 0; }
    for (int j = i; j < E_NUM * 64; j += blockDim.x) g_done[j] = 0;
}

__global__ void zero_out_kernel(float* __restrict__ out) {
    int i = blockIdx.x * blockDim.x + threadIdx.x;          // T*H/4 threads
    ((float4*)out)[i] = make_float4(0.f, 0.f, 0.f, 0.f);
}

// One warp per token: router logits + top-2, AND writes the fp16 copy of x.
__global__ void router_kernel(const float* __restrict__ x,
                              const float* __restrict__ wg) {
    int warp = threadIdx.x >> 5, lane = threadIdx.x & 31;
    int t = blockIdx.x * 8 + warp;
    if (t >= T_TOK) return;
    float acc[E_NUM];
#pragma unroll
    for (int e = 0; e < E_NUM; e++) acc[e] = 0.f;
    const float4* xr = (const float4*)(x + (size_t)t * H_DIM);
    __half2* xh = (__half2*)(g_xh + (size_t)t * H_DIM);
    for (int h4 = lane; h4 < H_DIM / 4; h4 += 32) {
        float4 xv = xr[h4];
        xh[h4 * 2 + 0] = __floats2half2_rn(xv.x, xv.y);
        xh[h4 * 2 + 1] = __floats2half2_rn(xv.z, xv.w);
#pragma unroll
        for (int e = 0; e < E_NUM; e++) {
            float4 wv = ((const float4*)(wg + (size_t)e * H_DIM))[h4];
            acc[e] += xv.x * wv.x + xv.y * wv.y + xv.z * wv.z + xv.w * wv.w;
        }
    }
#pragma unroll
    for (int e = 0; e < E_NUM; e++)
#pragma unroll
        for (int off = 16; off; off >>= 1)
            acc[e] += __shfl_xor_sync(0xffffffffu, acc[e], off);
    if (lane == 0) {
        int i0 = 0;
        for (int e = 1; e < E_NUM; e++) if (acc[e] > acc[i0]) i0 = e;
        int i1 = (i0 == 0) ? 1 : 0;
        for (int e = 0; e < E_NUM; e++) if (e != i0 && acc[e] > acc[i1]) i1 = e;
        float w0 = 1.f / (1.f + expf(acc[i1] - acc[i0]));
        g_topidx[2 * t] = i0; g_topidx[2 * t + 1] = i1;
        g_topw[2 * t] = w0;   g_topw[2 * t + 1] = 1.f - w0;
        atomicAdd(&g_counts[i0], 1);
        atomicAdd(&g_counts[i1], 1);
    }
}

__global__ void scan_kernel() {
    if (threadIdx.x == 0) {
        int s = 0;
        for (int e = 0; e < E_NUM; e++) { g_offsets[e] = s; s += g_counts[e]; }
        g_offsets[E_NUM] = s;
    }
}

__global__ void scatter_kernel() {
    int t = blockIdx.x * blockDim.x + threadIdx.x;
    if (t >= T_TOK) return;
#pragma unroll
    for (int k = 0; k < 2; k++) {
        int e = g_topidx[2 * t + k];
        int pos = atomicAdd(&g_cursors[e], 1);
        int glob = g_offsets[e] + pos;
        g_bucket[glob] = t;
        g_wbuf[glob] = g_topw[2 * t + k];
    }
}

// ---------------- fused fp16 mma grouped GEMM (both phases, one launch) ----------------
// 4 warps x (64x64), tile 128x128, BK=64, NSTG=3 (96KB dyn), 2 CTAs/SM.
// Phase 0 (bids 0..8191): y = silu(x@w1^T)*(x@w3^T) -> g_yh fp16; on completion
//   atomicAdd(g_done[e*64+mblk]). Phase 1 (bids 8192..): spin until all 16
//   phase-0 blocks of (e, mblk) are done, then z = y@w2^T and
//   out[token] += w * z via fp32 atomicAdd (2 adds/elem onto zeroed buffer ->
//   deterministic). Deadlock-free under monotone bid dispatch: phase-1 blocks
//   are only resident after every phase-0 block is resident-or-retired.
static constexpr int BM = 128, BN = 128, BK = 64;      // BK in halves (128B fp16 rows)
static constexpr int NSTG = 3;
static constexpr int MAT_B = 128 * 128;                // 16384 bytes per fp16 tile
static constexpr int STG_B = 2 * MAT_B;                // 32768 per stage
static constexpr int SMEM_BYTES = NSTG * STG_B;        // 98304
static constexpr int NB1 = 16 * 64 * E_NUM;            // 8192 phase-0 blocks

template <int MODE>
__device__ __forceinline__ void gemm_body(int bx, int by, int bz,
                                          const float* __restrict__ W0,
                                          const float* __restrict__ W1,
                                          float* __restrict__ out,
                                          char* smem)
{
    constexpr int KD = (MODE == 0) ? H_DIM : I_DIM;
    constexpr int NK = KD / BK;                         // 32 / 16

    const int e    = bz;
    const int row0 = g_offsets[e];
    const int cnt  = g_offsets[e + 1] - row0;
    const int m0   = by * BM;
    if (m0 >= cnt) return;

    const uint32_t smb = (uint32_t)__cvta_generic_to_shared(smem);
    const int tid = threadIdx.x;                        // 0..127
    const int wid = tid >> 5, lane = tid & 31;
    const int wm = wid & 1, wn = wid >> 1;              // 2(M) x 2(N) warps
    const int mbase = wm * 64, nbase = wn * 64;

    // Phase 1: wait for all 16 phase-0 producers of this (e, m-block).
    if (MODE == 1) {
        if (tid == 0) {
            while (atomicAdd(&g_done[e * 64 + by], 0) < 16) __nanosleep(128);
        }
        __syncthreads();
        __threadfence();
    }

    const int n0I = bx * 64;                            // MODE 0
    const int n0  = bx * BN;                            // MODE 1

    const int r8 = tid >> 3;                            // 0..15
    const int c8 = tid & 7;

    // ---- A: 8 cp.async chunks (16B) per thread per stage; chunk q -> row 16q+r8 ----
    const __half* gpA[8];
#pragma unroll
    for (int q = 0; q < 8; q++) {
        int r = q * 16 + r8;
        int lr = m0 + r; if (lr >= cnt) lr = cnt - 1;
        size_t arow = (MODE == 0) ? (size_t)g_bucket[row0 + lr] * KD
                                  : (size_t)(row0 + lr) * KD;
        gpA[q] = ((MODE == 0) ? g_xh : g_yh) + arow + c8 * 8;
    }
    // ---- B: 8 chunks (32B fp32 -> 16B fp16) per thread per stage ----
    const float4* gpB[8];
#pragma unroll
    for (int q = 0; q < 8; q++) {
        int r = q * 16 + r8;
        const float* bb;
        if (MODE == 0)
            bb = (r < 64) ? (W0 + ((size_t)e * I_DIM + (n0I + r)) * KD)
                          : (W1 + ((size_t)e * I_DIM + (n0I + r - 64)) * KD);
        else
            bb = W0 + ((size_t)e * H_DIM + (n0 + r)) * KD;
        gpB[q] = (const float4*)(bb + c8 * 8);
    }
    uint32_t soA[8], soB[8];
#pragma unroll
    for (int q = 0; q < 8; q++) {
        int r = q * 16 + r8;
        soA[q] = (uint32_t)SWZ128(r * 128 + c8 * 16);
        soB[q] = (uint32_t)MAT_B + (uint32_t)SWZ128(r * 128 + c8 * 16);
    }

    // ---- ldmatrix address bases ----
    const int lrow = lane & 15;
    const uint32_t kc16 = (uint32_t)(lane >> 4) * 16;
    uint32_t aRaw[4], aM[4], bRaw[4], bM[4];
#pragma unroll
    for (int i = 0; i < 4; i++) {
        int r = mbase + i * 16 + lrow;
        aRaw[i] = (uint32_t)r * 128 + kc16;
        aM[i] = (uint32_t)(r & 7) << 4;
    }
#pragma unroll
    for (int j = 0; j < 4; j++) {
        int r = nbase + j * 16 + lrow;
        bRaw[j] = (uint32_t)r * 128 + kc16;
        bM[j] = (uint32_t)(r & 7) << 4;
    }

    float acc[4][8][4];
#pragma unroll
    for (int i = 0; i < 4; i++)
#pragma unroll
        for (int j = 0; j < 8; j++)
#pragma unroll
            for (int q = 0; q < 4; q++) acc[i][j][q] = 0.f;

    // ---- prologue ----
#pragma unroll
    for (int s = 0; s < NSTG - 1; s++) {
        uint32_t base = smb + (uint32_t)s * STG_B;
#pragma unroll
        for (int q = 0; q < 8; q++) { cp16(base + soA[q], gpA[q]); gpA[q] += BK; }
#pragma unroll
        for (int q = 0; q < 8; q++) {
            float4 v0 = gpB[q][0], v1 = gpB[q][1];
            gpB[q] += BK / 4;
            uint4 h;
            h.x = h2u(__floats2half2_rn(v0.x, v0.y));
            h.y = h2u(__floats2half2_rn(v0.z, v0.w));
            h.z = h2u(__floats2half2_rn(v1.x, v1.y));
            h.w = h2u(__floats2half2_rn(v1.z, v1.w));
            *(uint4*)(smem + (size_t)s * STG_B + soB[q]) = h;
        }
        cp_commit();
    }

    // ---- mainloop ----
    for (int it = 0; it < NK; it++) {
        cp_wait<NSTG - 2>();
        __syncthreads();

        const bool act = (it + NSTG - 1 < NK);
        const uint32_t slot = (uint32_t)((it + NSTG - 1) % NSTG);
        const uint32_t nb = slot * STG_B;

        float4 br0[4], br1[4];
        if (act) {
            uint32_t base = smb + nb;
#pragma unroll
            for (int q = 0; q < 8; q++) { cp16(base + soA[q], gpA[q]); gpA[q] += BK; }
#pragma unroll
            for (int q = 0; q < 4; q++) {
                br0[q] = gpB[q][0]; br1[q] = gpB[q][1]; gpB[q] += BK / 4;
            }
        }

        const uint32_t sA = smb + (uint32_t)(it % NSTG) * STG_B;
        const uint32_t sB = sA + MAT_B;

        // ---- kk 0..1 ----
#pragma unroll
        for (int kk = 0; kk < 2; kk++) {
            uint32_t a[4][4], b[2][4];
#pragma unroll
            for (int i = 0; i < 4; i++)
                ldsm4(a[i], sA + ((aRaw[i] + kk * 32) ^ aM[i]));
#pragma unroll
            for (int jh = 0; jh < 2; jh++) {
#pragma unroll
                for (int jf = 0; jf < 2; jf++)
                    ldsm4(b[jf], sB + ((bRaw[jh * 2 + jf] + kk * 32) ^ bM[jh * 2 + jf]));
#pragma unroll
                for (int i = 0; i < 4; i++)
#pragma unroll
                    for (int jn = 0; jn < 4; jn++)
                        mma16816(acc[i][jh * 4 + jn], a[i],
                                 b[jn >> 1][jn & 1], b[jn >> 1][(jn & 1) + 2]);
            }
        }

        // STS batch0; LDG batch1
        if (act) {
#pragma unroll
            for (int q = 0; q < 4; q++) {
                uint4 h;
                h.x = h2u(__floats2half2_rn(br0[q].x, br0[q].y));
                h.y = h2u(__floats2half2_rn(br0[q].z, br0[q].w));
                h.z = h2u(__floats2half2_rn(br1[q].x, br1[q].y));
                h.w = h2u(__floats2half2_rn(br1[q].z, br1[q].w));
                *(uint4*)(smem + nb + soB[q]) = h;
            }
#pragma unroll
            for (int q = 4; q < 8; q++) {
                br0[q - 4] = gpB[q][0]; br1[q - 4] = gpB[q][1]; gpB[q] += BK / 4;
            }
        }

        // ---- kk 2..3 ----
#pragma unroll
        for (int kk = 2; kk < 4; kk++) {
            uint32_t a[4][4], b[2][4];
#pragma unroll
            for (int i = 0; i < 4; i++)
                ldsm4(a[i], sA + ((aRaw[i] + kk * 32) ^ aM[i]));
#pragma unroll
            for (int jh = 0; jh < 2; jh++) {
#pragma unroll
                for (int jf = 0; jf < 2; jf++)
                    ldsm4(b[jf], sB + ((bRaw[jh * 2 + jf] + kk * 32) ^ bM[jh * 2 + jf]));
#pragma unroll
                for (int i = 0; i < 4; i++)
#pragma unroll
                    for (int jn = 0; jn < 4; jn++)
                        mma16816(acc[i][jh * 4 + jn], a[i],
                                 b[jn >> 1][jn & 1], b[jn >> 1][(jn & 1) + 2]);
            }
        }

        // STS batch1
        if (act) {
#pragma unroll
            for (int q = 4; q < 8; q++) {
                uint4 h;
                h.x = h2u(__floats2half2_rn(br0[q - 4].x, br0[q - 4].y));
                h.y = h2u(__floats2half2_rn(br0[q - 4].z, br0[q - 4].w));
                h.z = h2u(__floats2half2_rn(br1[q - 4].x, br1[q - 4].y));
                h.w = h2u(__floats2half2_rn(br1[q - 4].z, br1[q - 4].w));
                *(uint4*)(smem + nb + soB[q]) = h;
            }
        }
        cp_commit();
    }

    // ---- epilogue: stage C (128x128 f32, 64KB) in smem ----
    __syncthreads();
    float* cb = (float*)smem;
#pragma unroll
    for (int i = 0; i < 4; i++) {
#pragma unroll
        for (int jn = 0; jn < 8; jn++) {
            int r = mbase + i * 16 + (lane >> 2);
            int c = nbase + jn * 8 + (lane & 3) * 2;
            cb[(size_t)r * BN + c]           = acc[i][jn][0];
            cb[(size_t)r * BN + c + 1]       = acc[i][jn][1];
            cb[(size_t)(r + 8) * BN + c]     = acc[i][jn][2];
            cb[(size_t)(r + 8) * BN + c + 1] = acc[i][jn][3];
        }
    }
    __syncthreads();

    if (MODE == 0) {
        int r = tid;                                     // one row per thread
        if (m0 + r < cnt) {
            __half2* dst = (__half2*)(g_yh + (size_t)(row0 + m0 + r) * I_DIM + n0I);
            const float* gr = cb + (size_t)r * BN;
            const float* ur = gr + 64;
#pragma unroll
            for (int c4 = 0; c4 < 16; c4++) {
                float4 g = *(const float4*)(gr + c4 * 4);
                float4 u = *(const float4*)(ur + c4 * 4);
                float4 v;
                v.x = g.x / (1.f + __expf(-g.x)) * u.x;
                v.y = g.y / (1.f + __expf(-g.y)) * u.y;
                v.z = g.z / (1.f + __expf(-g.z)) * u.z;
                v.w = g.w / (1.f + __expf(-g.w)) * u.w;
                dst[c4 * 2 + 0] = __floats2half2_rn(v.x, v.y);
                dst[c4 * 2 + 1] = __floats2half2_rn(v.z, v.w);
            }
        }
        // signal: this (e, m-block, n-block) producer is done
        __syncthreads();
        if (tid == 0) {
            __threadfence();
            atomicAdd(&g_done[e * 64 + by], 1);
        }
    } else {
        // out[token] += w * acc. Warp handles one row at a time (coalesced RED.F32).
        for (int r = wid; r < BM; r += 4) {
            if (m0 + r >= cnt) break;
            int gl = row0 + m0 + r;
            int tok = g_bucket[gl];
            float w = g_wbuf[gl];
            float* dst = out + (size_t)tok * H_DIM + n0 + lane * 4;
            const float* src = cb + (size_t)r * BN + lane * 4;
            float4 v = *(const float4*)src;
            atomicAdd(dst + 0, w * v.x);
            atomicAdd(dst + 1, w * v.y);
            atomicAdd(dst + 2, w * v.z);
            atomicAdd(dst + 3, w * v.w);
        }
    }
}

__global__ __launch_bounds__(128, 2)
void moe_fused_kernel(const float* __restrict__ w1,
                      const float* __restrict__ w3,
                      const float* __restrict__ w2,
                      float* __restrict__ out)
{
    extern __shared__ char smem[];
    int b = blockIdx.x;
    if (b < NB1) {
        gemm_body<0>(b & 15, (b >> 4) & 63, b >> 10, w1, w3, nullptr, smem);
    } else {
        b -= NB1;
        gemm_body<1>(b & 15, (b >> 4) & 63, b >> 10, w2, nullptr, out, smem);
    }
}

// ---------------- launch ----------------
extern "C" void kernel_launch(void* const* d_in, const int* in_sizes, int n_in,
                              void* d_out, int out_size) {
    const float* x  = (const float*)d_in[0];   // [T, H]
    const float* wg = (const float*)d_in[1];   // [E, H]
    const float* w1 = (const float*)d_in[2];   // [E, I, H]
    const float* w3 = (const float*)d_in[3];   // [E, I, H]
    const float* w2 = (const float*)d_in[4];   // [E, H, I]
    float* out = (float*)d_out;                // [T, H]

    cudaFuncSetAttribute(moe_fused_kernel,
                         cudaFuncAttributeMaxDynamicSharedMemorySize, SMEM_BYTES);

    init_kernel<<<1, 256>>>();
    router_kernel<<<T_TOK / 8, 256>>>(x, wg);
    scan_kernel<<<1, 32>>>();
    scatter_kernel<<<T_TOK / 256, 256>>>();
    zero_out_kernel<<<(T_TOK * H_DIM / 4) / 256, 256>>>(out);

    moe_fused_kernel<<<2 * NB1, 128, SMEM_BYTES>>>(w1, w3, w2, out);
}